// round 5
// baseline (speedup 1.0000x reference)
#include <cuda_runtime.h>

#define NB   10
#define HH   512
#define WW   512
#define OH   507
#define OW   507
#define TW   512      // output columns per block = full row
#define HRW  520      // hist-row width (519 hist cols, padded to /4)
#define XSW  520      // staged x columns (-2 .. 517)
#define CH   102      // output rows per block chunk (5 chunks cover 507)
#define NTH  512

#define RING_WORDS (NB * 8 * TW)     // 40960
#define HROW_WORDS (NB * HRW)        // 5200
#define XS_WORDS   (3 * XSW)         // 1560
#define SMEM_BYTES ((RING_WORDS + HROW_WORDS + XS_WORDS) * 4)  // 190880 B

__device__ __forceinline__ float pmod10(float v) {
    float r = fmodf(v, 10.0f);
    return (r < 0.0f) ? r + 10.0f : r;
}
__device__ __forceinline__ int slot3(int row) { return ((row % 3) + 3) % 3; }

__global__ __launch_bounds__(NTH, 1)
void hog_fused2(const float* __restrict__ x,
                const float* __restrict__ wgt,
                float* __restrict__ out)
{
    extern __shared__ float sm[];
    float* ring = sm;                              // [NB][8][TW]
    float* hrow = sm + RING_WORDS;                 // [NB][HRW]
    float* xs   = sm + RING_WORDS + HROW_WORDS;    // [3][XSW]
    __shared__ float wsh[18];

    const int tid = threadIdx.x;
    if (tid < 18) wsh[tid] = wgt[tid];

    const int n     = blockIdx.z;
    const int oy0   = blockIdx.y * CH;
    const int nrows = min(CH, OH - oy0);

    const int c      = tid & 127;                  // column-thread id (owns cols 4c..4c+3)
    const int g      = tid >> 7;                   // bin group 0..3
    const int bstart = (g < 2) ? 3 * g : 6 + 2 * (g - 2);   // 0,3,6,8
    const int bcnt   = (g < 2) ? 3 : 2;
    const int oc0    = 4 * c;

    // zero vertical ring buffer
    {
        float4 z = make_float4(0.f, 0.f, 0.f, 0.f);
        float4* r4 = (float4*)ring;
        for (int i = tid; i < RING_WORDS / 4; i += NTH) r4[i] = z;
    }

    const float* xbase = x + (size_t)n * HH * WW;

    auto load_xrow = [&](int row) {
        const int  sl  = slot3(row) * XSW;
        const bool rok = (row >= 0) && (row < HH);
        const float* src = xbase + (size_t)row * WW;
        for (int lx = tid; lx < XSW; lx += NTH) {
            int gc = lx - 2;
            float v = 0.0f;
            if (rok && gc >= 0 && gc < WW) v = src[gc];
            xs[sl + lx] = v;
        }
    };

    load_xrow(oy0 - 2);
    load_xrow(oy0 - 1);

    float acc[3][4];
#pragma unroll
    for (int k = 0; k < 3; k++) {
        acc[k][0] = 0.f; acc[k][1] = 0.f; acc[k][2] = 0.f; acc[k][3] = 0.f;
    }

    const int iters = nrows + 7;
    for (int it = 0; it < iters; it++) {
        const int hy = oy0 - 1 + it;

        __syncthreads();  // A: prev-iter sum reads / hist xs reads done

        // zero hist row (vectorized)
        {
            float4 z = make_float4(0.f, 0.f, 0.f, 0.f);
            float4* h4 = (float4*)hrow;
            for (int i = tid; i < HROW_WORDS / 4; i += NTH) h4[i] = z;
        }
        load_xrow(hy + 1);

        __syncthreads();  // B: hrow zeroed + x row staged

        // ---- per-pixel hist contribution, scatter into hrow ----
        if (hy >= 0 && hy < HH) {
            const int r0 = slot3(hy - 1) * XSW;
            const int r1 = slot3(hy)     * XSW;
            const int r2 = slot3(hy + 1) * XSW;
            for (int hl = tid; hl < TW + 7; hl += NTH) {
                const int hc = hl - 1;
                if (hc >= 0 && hc < WW) {
                    float a0 = xs[r0 + hl], a1 = xs[r0 + hl + 1], a2 = xs[r0 + hl + 2];
                    float b0 = xs[r1 + hl], b1 = xs[r1 + hl + 1], b2 = xs[r1 + hl + 2];
                    float c0 = xs[r2 + hl], c1 = xs[r2 + hl + 1], c2 = xs[r2 + hl + 2];

                    float gx = wsh[0]*a0 + wsh[1]*a1 + wsh[2]*a2
                             + wsh[3]*b0 + wsh[4]*b1 + wsh[5]*b2
                             + wsh[6]*c0 + wsh[7]*c1 + wsh[8]*c2;
                    float gy = wsh[9]*a0  + wsh[10]*a1 + wsh[11]*a2
                             + wsh[12]*b0 + wsh[13]*b1 + wsh[14]*b2
                             + wsh[15]*c0 + wsh[16]*c1 + wsh[17]*c2;

                    float nrm  = sqrtf(gx * gx + gy * gy);
                    float pint = atan2f(gx, gy) / 3.14159274f * 10.0f;

                    float fl = floorf(pint);
                    float cl = ceilf(pint);
                    float f  = pmod10(pint);
                    float bm = pmod10(fl);
                    float tm = pmod10(cl);
                    float t_v = nrm * (1.0f - (tm - f));
                    float b_v = nrm * (1.0f - (f - bm));

                    int ib = (int)fl % 10; if (ib < 0) ib += 10;
                    int ic = (int)cl % 10; if (ic < 0) ic += 10;

                    hrow[ib * HRW + hl] = b_v;
                    hrow[ic * HRW + hl] = (ic == ib) ? (b_v + t_v) : t_v;
                }
            }
        }

        __syncthreads();  // C: scatter visible

        // ---- sliding horizontal 8-sum (4 cols/thread, float4) + vertical ring ----
        const int r = it & 7;
#pragma unroll
        for (int k = 0; k < 3; k++) {
            if (k < bcnt) {
                const int b = bstart + k;
                const float4* hb = (const float4*)(hrow + b * HRW);
                float4 v0 = hb[c];
                float4 v1 = hb[c + 1];
                float4 v2 = hb[c + 2];
                float s0 = ((v0.x + v0.y) + (v0.z + v0.w))
                         + ((v1.x + v1.y) + (v1.z + v1.w));
                float s1 = s0 - v0.x + v2.x;
                float s2 = s1 - v0.y + v2.y;
                float s3 = s2 - v0.z + v2.z;

                float4* rb = (float4*)(ring + (b * 8 + r) * TW);
                float4 old = rb[c];
                acc[k][0] += s0 - old.x;
                acc[k][1] += s1 - old.y;
                acc[k][2] += s2 - old.z;
                acc[k][3] += s3 - old.w;
                rb[c] = make_float4(s0, s1, s2, s3);
            }
        }

        if (it >= 7) {
            const int oy = oy0 + it - 7;
#pragma unroll
            for (int k = 0; k < 3; k++) {
                if (k < bcnt) {
                    const int b = bstart + k;
                    float* op = out + (((size_t)n * NB + b) * OH + oy) * OW + oc0;
#pragma unroll
                    for (int j = 0; j < 4; j++)
                        if (oc0 + j < OW) op[j] = acc[k][j] * 0.015625f;
                }
            }
        }
    }
}

extern "C" void kernel_launch(void* const* d_in, const int* in_sizes, int n_in,
                              void* d_out, int out_size) {
    const float* x = (const float*)d_in[0];
    const float* w = (const float*)d_in[1];
    float* out = (float*)d_out;

    const int nbatch = in_sizes[0] / (HH * WW);  // 32

    cudaFuncSetAttribute(hog_fused2,
                         cudaFuncAttributeMaxDynamicSharedMemorySize, SMEM_BYTES);

    dim3 grid(1, (OH + CH - 1) / CH, nbatch);    // (1, 5, 32)
    hog_fused2<<<grid, NTH, SMEM_BYTES>>>(x, w, out);
}

// round 7
// speedup vs baseline: 1.7849x; 1.7849x over previous
#include <cuda_runtime.h>

#define NB   10
#define HH   512
#define WW   512
#define OH   507
#define OW   507
#define TW   128      // output columns per block
#define NC   32       // column-threads (each owns 4 cols)
#define HRW  136      // hist-row width: TW+7=135 hist cols, padded to /4
#define XSW  140      // staged x cols: TW+9=137, padded
#define CH   127      // output rows per block chunk (4 chunks cover 507)
#define NTH  128

__device__ __forceinline__ float pmod10(float v) {
    float r = fmodf(v, 10.0f);
    return (r < 0.0f) ? r + 10.0f : r;
}
__device__ __forceinline__ int slot3(int row) { return ((row % 3) + 3) % 3; }

__global__ __launch_bounds__(NTH)
void hog_fused4(const float* __restrict__ x,
                const float* __restrict__ wgt,
                float* __restrict__ out)
{
    __shared__ float ring[NB][8][TW];   // 40960 B  vertical 8-row hsum history
    __shared__ float hrow[NB][HRW];     //  5440 B  one hist row, dense
    __shared__ float xs[3][XSW];        //  1680 B  3-row input ring
    __shared__ float wsh[18];

    const int tid = threadIdx.x;
    if (tid < 18) wsh[tid] = wgt[tid];

    const int n    = blockIdx.z;
    const int ox0  = blockIdx.x * TW;
    const int oy0  = blockIdx.y * CH;
    const int nrows = min(CH, OH - oy0);

    const int c      = tid & (NC - 1);              // column-thread: cols 4c..4c+3
    const int g      = tid >> 5;                    // bin group 0..3
    const int bstart = (g < 2) ? 3 * g : 6 + 2 * (g - 2);   // 0,3,6,8
    const int bcnt   = (g < 2) ? 3 : 2;
    const int oc0    = 4 * c;
    const int ox     = ox0 + oc0;

    // zero the vertical ring buffer
    {
        float4 z = make_float4(0.f, 0.f, 0.f, 0.f);
        float4* r4 = (float4*)ring;
        for (int i = tid; i < NB * 8 * TW / 4; i += NTH) r4[i] = z;
    }

    const float* xbase = x + (size_t)n * HH * WW;

#define LOAD_XROW(ROW)                                                        \
    do {                                                                      \
        int _row = (ROW);                                                     \
        int _sl = slot3(_row);                                                \
        const bool _rok = (_row >= 0) && (_row < HH);                         \
        const float* _src = xbase + (size_t)_row * WW;                        \
        for (int lx = tid; lx < XSW; lx += NTH) {                             \
            int gc = ox0 - 2 + lx;                                            \
            float v = 0.0f;                                                   \
            if (_rok && gc >= 0 && gc < WW) v = _src[gc];                     \
            xs[_sl][lx] = v;                                                  \
        }                                                                     \
    } while (0)

    LOAD_XROW(oy0 - 2);
    LOAD_XROW(oy0 - 1);

    float acc[3][4];
#pragma unroll
    for (int k = 0; k < 3; k++)
#pragma unroll
        for (int j = 0; j < 4; j++) acc[k][j] = 0.f;

    const int iters = nrows + 7;
    for (int it = 0; it < iters; it++) {
        const int hy = oy0 - 1 + it;

        __syncthreads();  // A: previous-iter hsum reads & xs reads complete

        // zero hist row (float4, conflict-free)
        {
            float4 z = make_float4(0.f, 0.f, 0.f, 0.f);
            float4* h4 = (float4*)hrow;
#pragma unroll
            for (int i = tid; i < NB * HRW / 4; i += NTH) h4[i] = z;
        }
        LOAD_XROW(hy + 1);

        __syncthreads();  // B: hrow zeroed + x row staged

        // ---- per-pixel hist contribution (hist cols hl = 0..TW+6, STRIDED) ----
        if (hy >= 0 && hy < HH) {
            const int s0 = slot3(hy - 1);
            const int s1 = slot3(hy);
            const int s2 = slot3(hy + 1);
            for (int hl = tid; hl < TW + 7; hl += NTH) {
                const int hc = ox0 - 1 + hl;
                if (hc >= 0 && hc < WW) {
                    float a0 = xs[s0][hl], a1 = xs[s0][hl + 1], a2 = xs[s0][hl + 2];
                    float b0 = xs[s1][hl], b1 = xs[s1][hl + 1], b2 = xs[s1][hl + 2];
                    float c0 = xs[s2][hl], c1 = xs[s2][hl + 1], c2 = xs[s2][hl + 2];

                    float gx = wsh[0]*a0 + wsh[1]*a1 + wsh[2]*a2
                             + wsh[3]*b0 + wsh[4]*b1 + wsh[5]*b2
                             + wsh[6]*c0 + wsh[7]*c1 + wsh[8]*c2;
                    float gy = wsh[9]*a0  + wsh[10]*a1 + wsh[11]*a2
                             + wsh[12]*b0 + wsh[13]*b1 + wsh[14]*b2
                             + wsh[15]*c0 + wsh[16]*c1 + wsh[17]*c2;

                    float nrm  = sqrtf(gx * gx + gy * gy);
                    float pint = atan2f(gx, gy) / 3.14159274f * 10.0f;

                    float fl = floorf(pint);
                    float cl = ceilf(pint);
                    float f  = pmod10(pint);
                    float bm = pmod10(fl);
                    float tm = pmod10(cl);
                    float t_v = nrm * (1.0f - (tm - f));
                    float b_v = nrm * (1.0f - (f - bm));

                    int ib = (int)fl % 10; if (ib < 0) ib += 10;
                    int ic = (int)cl % 10; if (ic < 0) ic += 10;

                    hrow[ib][hl] = b_v;
                    hrow[ic][hl] = (ic == ib) ? (b_v + t_v) : t_v;
                }
            }
        }

        __syncthreads();  // C: scatter visible

        // ---- sliding horizontal 8-sum (4 cols/thread) + vertical ring ----
        const int r = it & 7;
#pragma unroll
        for (int k = 0; k < 3; k++) {
            if (k < bcnt) {
                const int b = bstart + k;
                const float4* hb = (const float4*)(&hrow[b][0]);
                float4 v0 = hb[c];
                float4 v1 = hb[c + 1];
                float4 v2 = hb[c + 2];
                float s0 = ((v0.x + v0.y) + (v0.z + v0.w))
                         + ((v1.x + v1.y) + (v1.z + v1.w));
                float s1 = s0 - v0.x + v2.x;
                float s2 = s1 - v0.y + v2.y;
                float s3 = s2 - v0.z + v2.z;

                float4* rb = (float4*)(&ring[b][r][0]);
                float4 old = rb[c];
                acc[k][0] += s0 - old.x;
                acc[k][1] += s1 - old.y;
                acc[k][2] += s2 - old.z;
                acc[k][3] += s3 - old.w;
                rb[c] = make_float4(s0, s1, s2, s3);
            }
        }

        if (it >= 7) {
            const int oy = oy0 + it - 7;
#pragma unroll
            for (int k = 0; k < 3; k++) {
                if (k < bcnt) {
                    const int b = bstart + k;
                    float* op = out + (((size_t)n * NB + b) * OH + oy) * OW + ox;
#pragma unroll
                    for (int j = 0; j < 4; j++)
                        if (ox + j < OW) op[j] = acc[k][j] * 0.015625f;
                }
            }
        }
    }
#undef LOAD_XROW
}

extern "C" void kernel_launch(void* const* d_in, const int* in_sizes, int n_in,
                              void* d_out, int out_size) {
    const float* x = (const float*)d_in[0];
    const float* w = (const float*)d_in[1];
    float* out = (float*)d_out;

    (void)n_in; (void)out_size; (void)in_sizes;

    dim3 grid((OW + TW - 1) / TW,   // 4
              (OH + CH - 1) / CH,   // 4
              32);                  // batch
    hog_fused4<<<grid, NTH>>>(x, w, out);
}